// round 1
// baseline (speedup 1.0000x reference)
#include <cuda_runtime.h>
#include <cstdint>
#include <math.h>

// ---------------------------------------------------------------------------
// Attention_37074157699274 : x[4,1024,32,256] -> QKV -> 8-head attn (n=32,d=64)
//                            -> out proj (512->256) + bias
// Round 0: 3-kernel tf32 mma.sync pipeline.
//   K1: qkv  = x @ W_qkv            [131072,256]x[256,1536]
//   K2: attn per (b,p,h) block      32768 blocks of 32 tokens
//   K3: out  = attn_o @ W_out + b   [131072,512]x[512,256]
// ---------------------------------------------------------------------------

#define TOKENS   131072          // 4*1024*32
#define GROUPS   4096            // 4*1024  (independent 32-token groups)
#define DIMX     256
#define NQKV     1536
#define INNER    512
#define HEADS    8
#define DH       64
#define ATT_SCALE 0.125f         // 64^-0.5

// scratch (static device globals: allocation-free)
__device__ float g_qkv[(size_t)TOKENS * NQKV];    // 805 MB
__device__ float g_attn[(size_t)TOKENS * INNER];  // 268 MB

// ------------------------- helpers -----------------------------------------

__device__ __forceinline__ uint32_t f2tf32(float x) {
    uint32_t u;
    asm("cvt.rna.tf32.f32 %0, %1;" : "=r"(u) : "f"(x));
    return u;
}
__device__ __forceinline__ float f2tf32f(float x) {
    return __uint_as_float(f2tf32(x));
}

__device__ __forceinline__ void mma_tf32(float c[4], const uint32_t a[4],
                                         uint32_t b0, uint32_t b1) {
    asm volatile(
        "mma.sync.aligned.m16n8k8.row.col.f32.tf32.tf32.f32 "
        "{%0,%1,%2,%3}, {%4,%5,%6,%7}, {%8,%9}, {%0,%1,%2,%3};\n"
        : "+f"(c[0]), "+f"(c[1]), "+f"(c[2]), "+f"(c[3])
        : "r"(a[0]), "r"(a[1]), "r"(a[2]), "r"(a[3]), "r"(b0), "r"(b1));
}

// ------------------------- K1 / K3: tiled GEMM ------------------------------
// C[M,N] = A[M,K] @ B[K,N] (+ bias), tf32 mma, CTA tile 128x128, K-chunk 32.
// 256 threads = 8 warps, warp grid 4(M) x 2(N): each warp 32x64.

__global__ __launch_bounds__(256, 2)
void gemm_tf32(const float* __restrict__ A, const float* __restrict__ B,
               float* __restrict__ C, int K, int N,
               const float* __restrict__ bias)
{
    __shared__ float As[128][36];   // 36-float rows: conflict-free frag reads
    __shared__ float Bs[32][136];   // 136-float rows: conflict-free frag reads

    const int t    = threadIdx.x;
    const int lane = t & 31;
    const int warp = t >> 5;
    const int warpM = warp & 3;     // 0..3 -> rows [warpM*32, +32)
    const int warpN = warp >> 2;    // 0..1 -> cols [warpN*64, +64)

    const long rowBase = (long)blockIdx.y * 128;
    const int  colBase = blockIdx.x * 128;

    float acc[2][8][4];
    #pragma unroll
    for (int mt = 0; mt < 2; mt++)
        #pragma unroll
        for (int nt = 0; nt < 8; nt++)
            #pragma unroll
            for (int i = 0; i < 4; i++) acc[mt][nt][i] = 0.f;

    for (int kc = 0; kc < K; kc += 32) {
        // stage A tile [128][32] (tf32-rounded)
        #pragma unroll
        for (int i = 0; i < 4; i++) {
            int idx = i * 256 + t;
            int r  = idx >> 3;            // 0..127
            int kk = (idx & 7) * 4;       // 0,4,...,28
            float4 v = *(const float4*)(A + (rowBase + r) * K + kc + kk);
            As[r][kk + 0] = f2tf32f(v.x);
            As[r][kk + 1] = f2tf32f(v.y);
            As[r][kk + 2] = f2tf32f(v.z);
            As[r][kk + 3] = f2tf32f(v.w);
        }
        // stage B tile [32][128]
        #pragma unroll
        for (int i = 0; i < 4; i++) {
            int idx = i * 256 + t;
            int kr = idx >> 5;            // 0..31
            int nn = (idx & 31) * 4;      // 0..124
            float4 v = *(const float4*)(B + (long)(kc + kr) * N + colBase + nn);
            Bs[kr][nn + 0] = f2tf32f(v.x);
            Bs[kr][nn + 1] = f2tf32f(v.y);
            Bs[kr][nn + 2] = f2tf32f(v.z);
            Bs[kr][nn + 3] = f2tf32f(v.w);
        }
        __syncthreads();

        #pragma unroll
        for (int ks = 0; ks < 4; ks++) {
            const int k0 = ks * 8;
            uint32_t a[2][4];
            #pragma unroll
            for (int mt = 0; mt < 2; mt++) {
                int r0 = warpM * 32 + mt * 16 + (lane >> 2);
                a[mt][0] = __float_as_uint(As[r0    ][k0     + (lane & 3)]);
                a[mt][1] = __float_as_uint(As[r0 + 8][k0     + (lane & 3)]);
                a[mt][2] = __float_as_uint(As[r0    ][k0 + 4 + (lane & 3)]);
                a[mt][3] = __float_as_uint(As[r0 + 8][k0 + 4 + (lane & 3)]);
            }
            #pragma unroll
            for (int nt = 0; nt < 8; nt++) {
                int c0 = warpN * 64 + nt * 8 + (lane >> 2);
                uint32_t b0 = __float_as_uint(Bs[k0     + (lane & 3)][c0]);
                uint32_t b1 = __float_as_uint(Bs[k0 + 4 + (lane & 3)][c0]);
                mma_tf32(acc[0][nt], a[0], b0, b1);
                mma_tf32(acc[1][nt], a[1], b0, b1);
            }
        }
        __syncthreads();
    }

    // epilogue
    #pragma unroll
    for (int mt = 0; mt < 2; mt++) {
        long row = rowBase + warpM * 32 + mt * 16 + (lane >> 2);
        #pragma unroll
        for (int nt = 0; nt < 8; nt++) {
            int col = colBase + warpN * 64 + nt * 8 + 2 * (lane & 3);
            float b0 = 0.f, b1 = 0.f;
            if (bias) { b0 = bias[col]; b1 = bias[col + 1]; }
            float2 v0 = make_float2(acc[mt][nt][0] + b0, acc[mt][nt][1] + b1);
            float2 v1 = make_float2(acc[mt][nt][2] + b0, acc[mt][nt][3] + b1);
            *(float2*)(C + row * N + col)       = v0;
            *(float2*)(C + (row + 8) * N + col) = v1;
        }
    }
}

// ------------------------- K2: attention core -------------------------------
// One block per (group, head). 128 threads = 4 warps.
// S = (Q K^T) * scale  (32x32, K=64) ; softmax rows ; O = P V (32x64, K=32).

__global__ __launch_bounds__(128)
void attn_core(const float* __restrict__ qkv, float* __restrict__ o)
{
    __shared__ float Qs[32][68];
    __shared__ float Ks[32][68];
    __shared__ float Vs[32][72];
    __shared__ float S [32][36];

    const int t    = threadIdx.x;
    const int lane = t & 31;
    const int warp = t >> 5;
    const int g    = blockIdx.x;
    const int h    = g & 7;
    const long tokBase = (long)(g >> 3) * 32;

    const float* base = qkv + tokBase * NQKV;

    // load Q/K/V tiles [32][64], tf32-rounded
    #pragma unroll
    for (int i = 0; i < 4; i++) {
        int idx = i * 128 + t;
        int r  = idx >> 4;          // 0..31
        int cc = (idx & 15) * 4;    // 0..60
        const float* rowp = base + (long)r * NQKV + h * DH + cc;
        float4 q = *(const float4*)(rowp);
        float4 k = *(const float4*)(rowp + 512);
        float4 v = *(const float4*)(rowp + 1024);
        Qs[r][cc+0]=f2tf32f(q.x); Qs[r][cc+1]=f2tf32f(q.y);
        Qs[r][cc+2]=f2tf32f(q.z); Qs[r][cc+3]=f2tf32f(q.w);
        Ks[r][cc+0]=f2tf32f(k.x); Ks[r][cc+1]=f2tf32f(k.y);
        Ks[r][cc+2]=f2tf32f(k.z); Ks[r][cc+3]=f2tf32f(k.w);
        Vs[r][cc+0]=f2tf32f(v.x); Vs[r][cc+1]=f2tf32f(v.y);
        Vs[r][cc+2]=f2tf32f(v.z); Vs[r][cc+3]=f2tf32f(v.w);
    }
    __syncthreads();

    // ---- S = Q K^T : warp w -> mtile (w&1), ntiles {(w>>1)*2, +1}
    const int mt  = warp & 1;
    const int ntb = (warp >> 1) * 2;
    float sacc[2][4] = {{0.f,0.f,0.f,0.f},{0.f,0.f,0.f,0.f}};
    #pragma unroll
    for (int ks = 0; ks < 8; ks++) {
        int k0 = ks * 8;
        int r0 = mt * 16 + (lane >> 2);
        uint32_t a[4];
        a[0] = __float_as_uint(Qs[r0    ][k0     + (lane & 3)]);
        a[1] = __float_as_uint(Qs[r0 + 8][k0     + (lane & 3)]);
        a[2] = __float_as_uint(Qs[r0    ][k0 + 4 + (lane & 3)]);
        a[3] = __float_as_uint(Qs[r0 + 8][k0 + 4 + (lane & 3)]);
        #pragma unroll
        for (int n = 0; n < 2; n++) {
            int c0 = (ntb + n) * 8 + (lane >> 2);
            uint32_t b0 = __float_as_uint(Ks[c0][k0     + (lane & 3)]);
            uint32_t b1 = __float_as_uint(Ks[c0][k0 + 4 + (lane & 3)]);
            mma_tf32(sacc[n], a, b0, b1);
        }
    }
    #pragma unroll
    for (int n = 0; n < 2; n++) {
        int row = mt * 16 + (lane >> 2);
        int col = (ntb + n) * 8 + 2 * (lane & 3);
        S[row    ][col    ] = sacc[n][0] * ATT_SCALE;
        S[row    ][col + 1] = sacc[n][1] * ATT_SCALE;
        S[row + 8][col    ] = sacc[n][2] * ATT_SCALE;
        S[row + 8][col + 1] = sacc[n][3] * ATT_SCALE;
    }
    __syncthreads();

    // ---- softmax rows (32 rows, 32 cols)
    if (t < 32) {
        float m = -1e30f;
        #pragma unroll
        for (int j = 0; j < 32; j++) m = fmaxf(m, S[t][j]);
        float s = 0.f;
        #pragma unroll
        for (int j = 0; j < 32; j++) {
            float e = __expf(S[t][j] - m);
            S[t][j] = e;
            s += e;
        }
        float inv = 1.f / s;
        #pragma unroll
        for (int j = 0; j < 32; j++) S[t][j] *= inv;
    }
    __syncthreads();

    // ---- O = P V : warp w -> mtile (w&1), ntiles {(w>>1)*4 .. +3}
    const int nt4 = (warp >> 1) * 4;
    float oacc[4][4];
    #pragma unroll
    for (int n = 0; n < 4; n++)
        #pragma unroll
        for (int i = 0; i < 4; i++) oacc[n][i] = 0.f;

    #pragma unroll
    for (int ks = 0; ks < 4; ks++) {
        int k0 = ks * 8;
        int r0 = mt * 16 + (lane >> 2);
        uint32_t a[4];
        a[0] = f2tf32(S[r0    ][k0     + (lane & 3)]);
        a[1] = f2tf32(S[r0 + 8][k0     + (lane & 3)]);
        a[2] = f2tf32(S[r0    ][k0 + 4 + (lane & 3)]);
        a[3] = f2tf32(S[r0 + 8][k0 + 4 + (lane & 3)]);
        #pragma unroll
        for (int n = 0; n < 4; n++) {
            int c0 = (nt4 + n) * 8 + (lane >> 2);
            uint32_t b0 = __float_as_uint(Vs[k0     + (lane & 3)][c0]);
            uint32_t b1 = __float_as_uint(Vs[k0 + 4 + (lane & 3)][c0]);
            mma_tf32(oacc[n], a, b0, b1);
        }
    }

    float* obase = o + tokBase * INNER + h * DH;
    #pragma unroll
    for (int n = 0; n < 4; n++) {
        int row = mt * 16 + (lane >> 2);
        int col = (nt4 + n) * 8 + 2 * (lane & 3);
        *(float2*)(obase + (long)row * INNER + col) =
            make_float2(oacc[n][0], oacc[n][1]);
        *(float2*)(obase + (long)(row + 8) * INNER + col) =
            make_float2(oacc[n][2], oacc[n][3]);
    }
}

// ------------------------- launch -------------------------------------------

extern "C" void kernel_launch(void* const* d_in, const int* in_sizes, int n_in,
                              void* d_out, int out_size)
{
    const float* x     = (const float*)d_in[0];
    const float* W_qkv = (const float*)d_in[1];
    const float* W_out = (const float*)d_in[2];
    const float* b_out = (const float*)d_in[3];
    float* out = (float*)d_out;

    float* qkv = nullptr;
    float* att = nullptr;
    cudaGetSymbolAddress((void**)&qkv, g_qkv);
    cudaGetSymbolAddress((void**)&att, g_attn);

    // K1: qkv = x @ W_qkv   (M=131072, K=256, N=1536)
    gemm_tf32<<<dim3(NQKV / 128, TOKENS / 128), 256>>>(
        x, W_qkv, qkv, DIMX, NQKV, nullptr);

    // K2: attention core (4096 groups * 8 heads)
    attn_core<<<GROUPS * HEADS, 128>>>(qkv, att);

    // K3: out = att @ W_out + b_out   (M=131072, K=512, N=256)
    gemm_tf32<<<dim3(DIMX / 128, TOKENS / 128), 256>>>(
        att, W_out, out, INNER, DIMX, b_out);
}